// round 1
// baseline (speedup 1.0000x reference)
#include <cuda_runtime.h>
#include <math.h>

#define D_MODEL 768
#define D_INNER 1536
#define D_STATE 16
#define DT_RANK 48
#define D_CONV  4
#define NLAYER  2
#define BATCH   2
#define SEQ     2048
#define NTOK    (BATCH*SEQ)            /* 4096 */
#define XPROJ_N (DT_RANK + 2*D_STATE)  /* 80   */

// ---------------- scratch (device globals: no allocations allowed) ----------
__device__ __align__(16) float g_h [NTOK*D_MODEL];       // residual stream
__device__ __align__(16) float g_xn[NTOK*D_MODEL];       // layernorm out
__device__ __align__(16) float g_xz[NTOK*2*D_INNER];     // in_proj out (u|z)
__device__ __align__(16) float g_u [NTOK*D_INNER];       // conv+silu out
__device__ __align__(16) float g_xd[NTOK*XPROJ_N];       // x_proj out
__device__ __align__(16) float g_dt[NTOK*D_INNER];       // softplus(dt)
__device__ __align__(16) float g_y [NTOK*D_INNER];       // scan out * silu(z)

// ---------------- layernorm -------------------------------------------------
__global__ void ln_kernel(const float* __restrict__ in,
                          const float* __restrict__ w,
                          const float* __restrict__ b,
                          float* __restrict__ out)
{
    int row = blockIdx.x;
    const float* xr = in + (size_t)row * D_MODEL;
    float s = 0.f, q = 0.f;
    for (int i = threadIdx.x; i < D_MODEL; i += blockDim.x) {
        float v = xr[i]; s += v; q += v * v;
    }
    __shared__ float sh_s[8], sh_q[8];
    #pragma unroll
    for (int o = 16; o; o >>= 1) {
        s += __shfl_xor_sync(0xffffffffu, s, o);
        q += __shfl_xor_sync(0xffffffffu, q, o);
    }
    int wid = threadIdx.x >> 5;
    if ((threadIdx.x & 31) == 0) { sh_s[wid] = s; sh_q[wid] = q; }
    __syncthreads();
    if (threadIdx.x < 32) {
        s = (threadIdx.x < 8) ? sh_s[threadIdx.x] : 0.f;
        q = (threadIdx.x < 8) ? sh_q[threadIdx.x] : 0.f;
        #pragma unroll
        for (int o = 4; o; o >>= 1) {
            s += __shfl_xor_sync(0xffffffffu, s, o);
            q += __shfl_xor_sync(0xffffffffu, q, o);
        }
        if (threadIdx.x == 0) { sh_s[0] = s; sh_q[0] = q; }
    }
    __syncthreads();
    float mu  = sh_s[0] * (1.f / D_MODEL);
    float var = sh_q[0] * (1.f / D_MODEL) - mu * mu;
    float inv = rsqrtf(var + 1e-5f);
    float* orow = out + (size_t)row * D_MODEL;
    for (int i = threadIdx.x; i < D_MODEL; i += blockDim.x)
        orow[i] = (xr[i] - mu) * inv * w[i] + b[i];
}

// ---------------- generic TN SGEMM: C[M,N] = A[M,K(lda)] * W[N,K(ldb)]^T ----
// EPI: 0 none, 1 +bias, 2 softplus(acc+bias), 3 +residual
template <int EPI>
__global__ __launch_bounds__(256)
void sgemm_kernel(const float* __restrict__ A, int lda,
                  const float* __restrict__ W, int ldb,
                  const float* __restrict__ bias,
                  const float* __restrict__ resid,
                  float* __restrict__ C,
                  int M, int N, int K)
{
    __shared__ float As[8][128];
    __shared__ float Bs[8][128];

    int tid = threadIdx.x;
    int tx = tid & 15, ty = tid >> 4;
    int row0 = blockIdx.y * 128, col0 = blockIdx.x * 128;

    int lr = tid >> 1;          // 0..127
    int lk = (tid & 1) * 4;     // 0 or 4

    float acc[8][8];
    #pragma unroll
    for (int i = 0; i < 8; i++)
        #pragma unroll
        for (int j = 0; j < 8; j++) acc[i][j] = 0.f;

    const float* Aptr = A + (size_t)(row0 + lr) * lda + lk;
    int nn = col0 + lr;
    bool bok = (nn < N);
    const float* Wptr = W + (size_t)(bok ? nn : 0) * ldb + lk;

    for (int k0 = 0; k0 < K; k0 += 8) {
        float4 av = *(const float4*)(Aptr + k0);
        float4 bv = bok ? *(const float4*)(Wptr + k0)
                        : make_float4(0.f, 0.f, 0.f, 0.f);
        As[lk + 0][lr] = av.x; As[lk + 1][lr] = av.y;
        As[lk + 2][lr] = av.z; As[lk + 3][lr] = av.w;
        Bs[lk + 0][lr] = bv.x; Bs[lk + 1][lr] = bv.y;
        Bs[lk + 2][lr] = bv.z; Bs[lk + 3][lr] = bv.w;
        __syncthreads();

        #pragma unroll
        for (int kk = 0; kk < 8; kk++) {
            float ar[8], br[8];
            *(float4*)&ar[0] = *(const float4*)&As[kk][ty * 8];
            *(float4*)&ar[4] = *(const float4*)&As[kk][ty * 8 + 4];
            *(float4*)&br[0] = *(const float4*)&Bs[kk][tx * 8];
            *(float4*)&br[4] = *(const float4*)&Bs[kk][tx * 8 + 4];
            #pragma unroll
            for (int i = 0; i < 8; i++)
                #pragma unroll
                for (int j = 0; j < 8; j++)
                    acc[i][j] = fmaf(ar[i], br[j], acc[i][j]);
        }
        __syncthreads();
    }

    #pragma unroll
    for (int i = 0; i < 8; i++) {
        int r = row0 + ty * 8 + i;
        #pragma unroll
        for (int j = 0; j < 8; j++) {
            int c = col0 + tx * 8 + j;
            if (c < N) {
                float v = acc[i][j];
                if (EPI == 1) v += bias[c];
                if (EPI == 2) {
                    v += bias[c];
                    v = (v > 20.f) ? v : log1pf(__expf(v));
                }
                if (EPI == 3) v += resid[(size_t)r * N + c];
                C[(size_t)r * N + c] = v;
            }
        }
    }
}

// ---------------- depthwise causal conv (width 4) + silu --------------------
__global__ void conv_silu_kernel(const float* __restrict__ cw,
                                 const float* __restrict__ cb)
{
    int idx = blockIdx.x * blockDim.x + threadIdx.x;
    if (idx >= NTOK * D_INNER) return;
    int d = idx % D_INNER;
    int t = idx / D_INNER;
    int l = t % SEQ;
    int b = t / SEQ;
    float acc = cb[d];
    #pragma unroll
    for (int k = 0; k < D_CONV; k++) {
        int l2 = l - (D_CONV - 1) + k;
        if (l2 >= 0)
            acc = fmaf(cw[d * D_CONV + k],
                       g_xz[(size_t)(b * SEQ + l2) * (2 * D_INNER) + d], acc);
    }
    g_u[idx] = acc / (1.f + __expf(-acc));   // silu
}

// ---------------- selective scan + gating -----------------------------------
// 16 lanes per channel (one per state); lane-group reduction for y.
__global__ void scan_kernel(const float* __restrict__ A_log,
                            const float* __restrict__ Dp)
{
    int warp = (blockIdx.x * blockDim.x + threadIdx.x) >> 5;
    int lane = threadIdx.x & 31;
    int s  = lane & 15;
    int ch = warp * 2 + (lane >> 4);
    if (ch >= BATCH * D_INNER) return;
    int b = ch / D_INNER;
    int d = ch % D_INNER;

    float Ac = -__expf(A_log[d * D_STATE + s]);
    float Dv = Dp[d];
    float h = 0.f;

    for (int l = 0; l < SEQ; ++l) {
        int t = b * SEQ + l;
        float dt = g_dt[(size_t)t * D_INNER + d];
        float u  = g_u [(size_t)t * D_INNER + d];
        float Bv = g_xd[t * XPROJ_N + DT_RANK + s];
        float Cv = g_xd[t * XPROJ_N + DT_RANK + D_STATE + s];
        h = fmaf(__expf(dt * Ac), h, dt * u * Bv);
        float p = h * Cv;
        p += __shfl_xor_sync(0xffffffffu, p, 8);
        p += __shfl_xor_sync(0xffffffffu, p, 4);
        p += __shfl_xor_sync(0xffffffffu, p, 2);
        p += __shfl_xor_sync(0xffffffffu, p, 1);
        if (s == 0) {
            float z = g_xz[(size_t)t * (2 * D_INNER) + D_INNER + d];
            float sil = z / (1.f + __expf(-z));
            g_y[(size_t)t * D_INNER + d] = (p + u * Dv) * sil;
        }
    }
}

// ---------------- host orchestration ----------------------------------------
extern "C" void kernel_launch(void* const* d_in, const int* in_sizes, int n_in,
                              void* d_out, int out_size)
{
    const float* x         = (const float*)d_in[0];
    const float* in_proj_w = (const float*)d_in[1];
    const float* conv_w    = (const float*)d_in[2];
    const float* conv_b    = (const float*)d_in[3];
    const float* x_proj_w  = (const float*)d_in[4];
    const float* dt_proj_w = (const float*)d_in[5];
    const float* dt_proj_b = (const float*)d_in[6];
    const float* A_log     = (const float*)d_in[7];
    const float* D_param   = (const float*)d_in[8];
    const float* out_proj_w= (const float*)d_in[9];
    const float* ln_w      = (const float*)d_in[10];
    const float* ln_b      = (const float*)d_in[11];
    const float* fnorm_w   = (const float*)d_in[12];
    const float* fnorm_b   = (const float*)d_in[13];
    const float* proj_w    = (const float*)d_in[14];
    const float* proj_b    = (const float*)d_in[15];

    float *h, *xn, *xz, *u, *xd, *dt, *y;
    cudaGetSymbolAddress((void**)&h,  g_h);
    cudaGetSymbolAddress((void**)&xn, g_xn);
    cudaGetSymbolAddress((void**)&xz, g_xz);
    cudaGetSymbolAddress((void**)&u,  g_u);
    cudaGetSymbolAddress((void**)&xd, g_xd);
    cudaGetSymbolAddress((void**)&dt, g_dt);
    cudaGetSymbolAddress((void**)&y,  g_y);

    // residual stream <- x
    cudaMemcpyAsync(h, x, sizeof(float) * (size_t)NTOK * D_MODEL,
                    cudaMemcpyDeviceToDevice);

    dim3 gIn (2 * D_INNER / 128, NTOK / 128);   // 24 x 32
    dim3 gXp (1,                 NTOK / 128);   // 80 cols -> 1 tile col
    dim3 gDt (D_INNER / 128,     NTOK / 128);   // 12 x 32
    dim3 gOut(D_MODEL / 128,     NTOK / 128);   //  6 x 32

    for (int i = 0; i < NLAYER; i++) {
        ln_kernel<<<NTOK, 256>>>(h, ln_w + i * D_MODEL, ln_b + i * D_MODEL, xn);

        sgemm_kernel<0><<<gIn, 256>>>(
            xn, D_MODEL,
            in_proj_w + (size_t)i * 2 * D_INNER * D_MODEL, D_MODEL,
            nullptr, nullptr, xz, NTOK, 2 * D_INNER, D_MODEL);

        conv_silu_kernel<<<(NTOK * D_INNER + 255) / 256, 256>>>(
            conv_w + (size_t)i * D_INNER * D_CONV, conv_b + i * D_INNER);

        sgemm_kernel<0><<<gXp, 256>>>(
            u, D_INNER,
            x_proj_w + (size_t)i * XPROJ_N * D_INNER, D_INNER,
            nullptr, nullptr, xd, NTOK, XPROJ_N, D_INNER);

        sgemm_kernel<2><<<gDt, 256>>>(
            xd, XPROJ_N,
            dt_proj_w + (size_t)i * D_INNER * DT_RANK, DT_RANK,
            dt_proj_b + i * D_INNER, nullptr, dt, NTOK, D_INNER, DT_RANK);

        scan_kernel<<<192, 256>>>(A_log + (size_t)i * D_INNER * D_STATE,
                                  D_param + i * D_INNER);

        sgemm_kernel<3><<<gOut, 256>>>(
            y, D_INNER,
            out_proj_w + (size_t)i * D_MODEL * D_INNER, D_INNER,
            nullptr, h, h, NTOK, D_MODEL, D_INNER);
    }

    ln_kernel<<<NTOK, 256>>>(h, fnorm_w, fnorm_b, xn);

    sgemm_kernel<1><<<gOut, 256>>>(
        xn, D_MODEL, proj_w, D_MODEL, proj_b, nullptr,
        (float*)d_out, NTOK, D_MODEL, D_MODEL);
}

// round 3
// speedup vs baseline: 1.0137x; 1.0137x over previous
#include <cuda_runtime.h>
#include <cstdint>
#include <math.h>

#define D_MODEL 768
#define D_INNER 1536
#define D_STATE 16
#define DT_RANK 48
#define D_CONV  4
#define NLAYER  2
#define BATCH   2
#define SEQ     2048
#define NTOK    (BATCH*SEQ)            /* 4096 */
#define XPROJ_N (DT_RANK + 2*D_STATE)  /* 80   */

// ---------------- scratch (device globals: no allocations allowed) ----------
__device__ __align__(16) float g_h [NTOK*D_MODEL];
__device__ __align__(16) float g_xn[NTOK*D_MODEL];
__device__ __align__(16) float g_xz[NTOK*2*D_INNER];
__device__ __align__(16) float g_u [NTOK*D_INNER];
__device__ __align__(16) float g_xd[NTOK*XPROJ_N];
__device__ __align__(16) float g_dt[NTOK*D_INNER];
__device__ __align__(16) float g_y [NTOK*D_INNER];

// ---- tf32 helpers ----------------------------------------------------------
__device__ __forceinline__ uint32_t ld_tf32(const float* p) {
    uint32_t r;
    asm("cvt.rna.tf32.f32 %0, %1;" : "=r"(r) : "f"(*p));
    return r;
}

#define LDSW 136   /* floats per k-row: (8*qk + qr) bank pattern -> conflict-free */

// ---------------- tf32 mma.sync TN GEMM: C[M,N] = A[M,K] * W[N,K]^T ---------
// EPI: 0 none, 1 +bias, 2 softplus(acc+bias), 3 +residual (in-place ok)
// ATOMIC: accumulate into C with atomicAdd (for split-K; requires EPI==0)
template <int EPI, bool ATOMIC>
__global__ __launch_bounds__(256)
void mgemm_kernel(const float* __restrict__ A, int lda,
                  const float* __restrict__ W, int ldb,
                  const float* __restrict__ bias,
                  const float* __restrict__ resid,
                  float* __restrict__ C,
                  int N, int K_len)
{
    __shared__ float As[2][16][LDSW];
    __shared__ float Bs[2][16][LDSW];

    const int tid  = threadIdx.x;
    const int lane = tid & 31;
    const int wid  = tid >> 5;
    const int wm   = (wid >> 2) * 64;   // warp M offset within tile
    const int wn   = (wid & 3) * 32;    // warp N offset within tile
    const int qk   = lane & 3;
    const int qr   = lane >> 2;

    const int row0 = blockIdx.y * 128;
    const int col0 = blockIdx.x * 128;
    const int K_begin = blockIdx.z * K_len;

    // loader mapping: each thread owns one row (lr) and 8 consecutive k (lkb..lkb+7)
    const int lr  = tid >> 1;
    const int lkb = (tid & 1) * 8;

    float acc[4][4][4];
    #pragma unroll
    for (int i = 0; i < 4; i++)
        #pragma unroll
        for (int j = 0; j < 4; j++)
            #pragma unroll
            for (int r = 0; r < 4; r++) acc[i][j][r] = 0.f;

    const int nchunk = K_len >> 4;      // K_len always a multiple of 16
    const float* Ap = A + (size_t)(row0 + lr) * lda + K_begin + lkb;
    const int wcol = col0 + lr;
    const bool bok = (wcol < N);
    const float* Wp = W + (size_t)(bok ? wcol : 0) * ldb + K_begin + lkb;

    float4 av0 = *(const float4*)(Ap);
    float4 av1 = *(const float4*)(Ap + 4);
    float4 bv0 = bok ? *(const float4*)(Wp)     : make_float4(0.f,0.f,0.f,0.f);
    float4 bv1 = bok ? *(const float4*)(Wp + 4) : make_float4(0.f,0.f,0.f,0.f);

    int buf = 0;
    for (int cc = 0; cc < nchunk; cc++) {
        As[buf][lkb+0][lr] = av0.x; As[buf][lkb+1][lr] = av0.y;
        As[buf][lkb+2][lr] = av0.z; As[buf][lkb+3][lr] = av0.w;
        As[buf][lkb+4][lr] = av1.x; As[buf][lkb+5][lr] = av1.y;
        As[buf][lkb+6][lr] = av1.z; As[buf][lkb+7][lr] = av1.w;
        Bs[buf][lkb+0][lr] = bv0.x; Bs[buf][lkb+1][lr] = bv0.y;
        Bs[buf][lkb+2][lr] = bv0.z; Bs[buf][lkb+3][lr] = bv0.w;
        Bs[buf][lkb+4][lr] = bv1.x; Bs[buf][lkb+5][lr] = bv1.y;
        Bs[buf][lkb+6][lr] = bv1.z; Bs[buf][lkb+7][lr] = bv1.w;
        __syncthreads();

        if (cc + 1 < nchunk) {                 // prefetch next tile (overlaps mma)
            const float* Ap2 = Ap + (cc + 1) * 16;
            const float* Wp2 = Wp + (cc + 1) * 16;
            av0 = *(const float4*)(Ap2);
            av1 = *(const float4*)(Ap2 + 4);
            if (bok) {
                bv0 = *(const float4*)(Wp2);
                bv1 = *(const float4*)(Wp2 + 4);
            }
        }

        #pragma unroll
        for (int ks = 0; ks < 16; ks += 8) {
            uint32_t a[4][4], b[4][2];
            #pragma unroll
            for (int i = 0; i < 4; i++) {
                const int am = wm + i * 16;
                a[i][0] = ld_tf32(&As[buf][ks + qk    ][am + qr    ]);
                a[i][1] = ld_tf32(&As[buf][ks + qk    ][am + qr + 8]);
                a[i][2] = ld_tf32(&As[buf][ks + qk + 4][am + qr    ]);
                a[i][3] = ld_tf32(&As[buf][ks + qk + 4][am + qr + 8]);
            }
            #pragma unroll
            for (int j = 0; j < 4; j++) {
                const int bn = wn + j * 8;
                b[j][0] = ld_tf32(&Bs[buf][ks + qk    ][bn + qr]);
                b[j][1] = ld_tf32(&Bs[buf][ks + qk + 4][bn + qr]);
            }
            #pragma unroll
            for (int i = 0; i < 4; i++)
                #pragma unroll
                for (int j = 0; j < 4; j++)
                    asm volatile(
                        "mma.sync.aligned.m16n8k8.row.col.f32.tf32.tf32.f32 "
                        "{%0,%1,%2,%3}, {%4,%5,%6,%7}, {%8,%9}, {%0,%1,%2,%3};"
                        : "+f"(acc[i][j][0]), "+f"(acc[i][j][1]),
                          "+f"(acc[i][j][2]), "+f"(acc[i][j][3])
                        : "r"(a[i][0]), "r"(a[i][1]), "r"(a[i][2]), "r"(a[i][3]),
                          "r"(b[j][0]), "r"(b[j][1]));
        }
        buf ^= 1;
    }

    // epilogue
    #pragma unroll
    for (int i = 0; i < 4; i++) {
        #pragma unroll
        for (int j = 0; j < 4; j++) {
            #pragma unroll
            for (int r = 0; r < 4; r++) {
                const int mrow = row0 + wm + i * 16 + qr + (r >> 1) * 8;
                const int mcol = col0 + wn + j * 8 + qk * 2 + (r & 1);
                if (mcol < N) {
                    float v = acc[i][j][r];
                    if (ATOMIC) {
                        atomicAdd(&C[(size_t)mrow * N + mcol], v);
                    } else {
                        if (EPI == 1) v += bias[mcol];
                        if (EPI == 2) {
                            v += bias[mcol];
                            v = (v > 20.f) ? v : log1pf(__expf(v));
                        }
                        if (EPI == 3) v += resid[(size_t)mrow * N + mcol];
                        C[(size_t)mrow * N + mcol] = v;
                    }
                }
            }
        }
    }
}

// ---------------- zero init (for split-K atomic target) ---------------------
__global__ void zero_kernel(float* __restrict__ p, int n)
{
    int i = blockIdx.x * blockDim.x + threadIdx.x;
    if (i < n) p[i] = 0.f;
}

// ---------------- layernorm -------------------------------------------------
__global__ void ln_kernel(const float* __restrict__ in,
                          const float* __restrict__ w,
                          const float* __restrict__ b,
                          float* __restrict__ out)
{
    int row = blockIdx.x;
    const float* xr = in + (size_t)row * D_MODEL;
    float s = 0.f, q = 0.f;
    for (int i = threadIdx.x; i < D_MODEL; i += blockDim.x) {
        float v = xr[i]; s += v; q += v * v;
    }
    __shared__ float sh_s[8], sh_q[8];
    #pragma unroll
    for (int o = 16; o; o >>= 1) {
        s += __shfl_xor_sync(0xffffffffu, s, o);
        q += __shfl_xor_sync(0xffffffffu, q, o);
    }
    int wid = threadIdx.x >> 5;
    if ((threadIdx.x & 31) == 0) { sh_s[wid] = s; sh_q[wid] = q; }
    __syncthreads();
    if (threadIdx.x < 32) {
        s = (threadIdx.x < 8) ? sh_s[threadIdx.x] : 0.f;
        q = (threadIdx.x < 8) ? sh_q[threadIdx.x] : 0.f;
        #pragma unroll
        for (int o = 4; o; o >>= 1) {
            s += __shfl_xor_sync(0xffffffffu, s, o);
            q += __shfl_xor_sync(0xffffffffu, q, o);
        }
        if (threadIdx.x == 0) { sh_s[0] = s; sh_q[0] = q; }
    }
    __syncthreads();
    float mu  = sh_s[0] * (1.f / D_MODEL);
    float var = sh_q[0] * (1.f / D_MODEL) - mu * mu;
    float inv = rsqrtf(var + 1e-5f);
    float* orow = out + (size_t)row * D_MODEL;
    for (int i = threadIdx.x; i < D_MODEL; i += blockDim.x)
        orow[i] = (xr[i] - mu) * inv * w[i] + b[i];
}

// ---------------- depthwise causal conv (width 4) + silu --------------------
__global__ void conv_silu_kernel(const float* __restrict__ cw,
                                 const float* __restrict__ cb)
{
    int idx = blockIdx.x * blockDim.x + threadIdx.x;
    if (idx >= NTOK * D_INNER) return;
    int d = idx % D_INNER;
    int t = idx / D_INNER;
    int l = t % SEQ;
    int b = t / SEQ;
    float acc = cb[d];
    #pragma unroll
    for (int k = 0; k < D_CONV; k++) {
        int l2 = l - (D_CONV - 1) + k;
        if (l2 >= 0)
            acc = fmaf(cw[d * D_CONV + k],
                       g_xz[(size_t)(b * SEQ + l2) * (2 * D_INNER) + d], acc);
    }
    g_u[idx] = acc / (1.f + __expf(-acc));
}

// ---------------- selective scan + gating -----------------------------------
__global__ void scan_kernel(const float* __restrict__ A_log,
                            const float* __restrict__ Dp)
{
    int warp = (blockIdx.x * blockDim.x + threadIdx.x) >> 5;
    int lane = threadIdx.x & 31;
    int s  = lane & 15;
    int ch = warp * 2 + (lane >> 4);
    if (ch >= BATCH * D_INNER) return;
    int b = ch / D_INNER;
    int d = ch % D_INNER;

    float Ac = -__expf(A_log[d * D_STATE + s]);
    float Dv = Dp[d];
    float h = 0.f;

    for (int l = 0; l < SEQ; ++l) {
        int t = b * SEQ + l;
        float dt = g_dt[(size_t)t * D_INNER + d];
        float u  = g_u [(size_t)t * D_INNER + d];
        float Bv = g_xd[t * XPROJ_N + DT_RANK + s];
        float Cv = g_xd[t * XPROJ_N + DT_RANK + D_STATE + s];
        h = fmaf(__expf(dt * Ac), h, dt * u * Bv);
        float p = h * Cv;
        p += __shfl_xor_sync(0xffffffffu, p, 8);
        p += __shfl_xor_sync(0xffffffffu, p, 4);
        p += __shfl_xor_sync(0xffffffffu, p, 2);
        p += __shfl_xor_sync(0xffffffffu, p, 1);
        if (s == 0) {
            float z = g_xz[(size_t)t * (2 * D_INNER) + D_INNER + d];
            float sil = z / (1.f + __expf(-z));
            g_y[(size_t)t * D_INNER + d] = (p + u * Dv) * sil;
        }
    }
}

// ---------------- host orchestration ----------------------------------------
extern "C" void kernel_launch(void* const* d_in, const int* in_sizes, int n_in,
                              void* d_out, int out_size)
{
    const float* x         = (const float*)d_in[0];
    const float* in_proj_w = (const float*)d_in[1];
    const float* conv_w    = (const float*)d_in[2];
    const float* conv_b    = (const float*)d_in[3];
    const float* x_proj_w  = (const float*)d_in[4];
    const float* dt_proj_w = (const float*)d_in[5];
    const float* dt_proj_b = (const float*)d_in[6];
    const float* A_log     = (const float*)d_in[7];
    const float* D_param   = (const float*)d_in[8];
    const float* out_proj_w= (const float*)d_in[9];
    const float* ln_w      = (const float*)d_in[10];
    const float* ln_b      = (const float*)d_in[11];
    const float* fnorm_w   = (const float*)d_in[12];
    const float* fnorm_b   = (const float*)d_in[13];
    const float* proj_w    = (const float*)d_in[14];
    const float* proj_b    = (const float*)d_in[15];

    float *h, *xn, *xz, *u, *xd, *dt, *y;
    cudaGetSymbolAddress((void**)&h,  g_h);
    cudaGetSymbolAddress((void**)&xn, g_xn);
    cudaGetSymbolAddress((void**)&xz, g_xz);
    cudaGetSymbolAddress((void**)&u,  g_u);
    cudaGetSymbolAddress((void**)&xd, g_xd);
    cudaGetSymbolAddress((void**)&dt, g_dt);
    cudaGetSymbolAddress((void**)&y,  g_y);

    cudaMemcpyAsync(h, x, sizeof(float) * (size_t)NTOK * D_MODEL,
                    cudaMemcpyDeviceToDevice);

    dim3 gIn (2 * D_INNER / 128, NTOK / 128, 1);   // 24 x 32
    dim3 gXp (1,                 NTOK / 128, 6);   // N=80, split-K x6
    dim3 gDt (D_INNER / 128,     NTOK / 128, 1);   // 12 x 32
    dim3 gOut(D_MODEL / 128,     NTOK / 128, 1);   //  6 x 32

    for (int i = 0; i < NLAYER; i++) {
        ln_kernel<<<NTOK, 256>>>(h, ln_w + i * D_MODEL, ln_b + i * D_MODEL, xn);

        mgemm_kernel<0, false><<<gIn, 256>>>(
            xn, D_MODEL,
            in_proj_w + (size_t)i * 2 * D_INNER * D_MODEL, D_MODEL,
            nullptr, nullptr, xz, 2 * D_INNER, D_MODEL);

        conv_silu_kernel<<<(NTOK * D_INNER + 255) / 256, 256>>>(
            conv_w + (size_t)i * D_INNER * D_CONV, conv_b + i * D_INNER);

        zero_kernel<<<(NTOK * XPROJ_N + 255) / 256, 256>>>(xd, NTOK * XPROJ_N);
        mgemm_kernel<0, true><<<gXp, 256>>>(
            u, D_INNER,
            x_proj_w + (size_t)i * XPROJ_N * D_INNER, D_INNER,
            nullptr, nullptr, xd, XPROJ_N, D_INNER / 6);

        mgemm_kernel<2, false><<<gDt, 256>>>(
            xd, XPROJ_N,
            dt_proj_w + (size_t)i * D_INNER * DT_RANK, DT_RANK,
            dt_proj_b + i * D_INNER, nullptr, dt, D_INNER, DT_RANK);

        scan_kernel<<<192, 256>>>(A_log + (size_t)i * D_INNER * D_STATE,
                                  D_param + i * D_INNER);

        mgemm_kernel<3, false><<<gOut, 256>>>(
            y, D_INNER,
            out_proj_w + (size_t)i * D_MODEL * D_INNER, D_INNER,
            nullptr, h, h, D_MODEL, D_INNER);
    }

    ln_kernel<<<NTOK, 256>>>(h, fnorm_w, fnorm_b, xn);

    mgemm_kernel<1, false><<<gOut, 256>>>(
        xn, D_MODEL, proj_w, D_MODEL, proj_b, nullptr,
        (float*)d_out, D_MODEL, D_MODEL);
}